// round 10
// baseline (speedup 1.0000x reference)
#include <cuda_runtime.h>
#include <math.h>

#define NEXP 16
#define MAX_T 4096

// Scratch (allocation-free per harness rules)
__device__ float g_probs[NEXP * MAX_T];   // [e][t] for coalesced aux reduce
__device__ float g_s0[MAX_T];
__device__ float g_s1[MAX_T];
__device__ int   g_i0[MAX_T];
__device__ int   g_i1[MAX_T];

// ---------------------------------------------------------------------------
// Kernel 1: gating. One warp per 2 tokens, plain float4 loop, 256-thr blocks
// (R6 proven config, timed ~12us). gw (131KB) L1-resident via __ldg.
// ---------------------------------------------------------------------------
__global__ void gate_kernel(const float4* __restrict__ hs,
                            const float4* __restrict__ gw,
                            int T, int H4) {
    int warp = (blockIdx.x * blockDim.x + threadIdx.x) >> 5;
    int lane = threadIdx.x & 31;
    int t0 = warp * 2;
    if (t0 >= T) return;
    int t1 = t0 + 1;
    bool has1 = (t1 < T);

    const float4* hrow0 = hs + (size_t)t0 * H4;
    const float4* hrow1 = hs + (size_t)(has1 ? t1 : t0) * H4;

    float acc0[NEXP], acc1[NEXP];
#pragma unroll
    for (int e = 0; e < NEXP; e++) { acc0[e] = 0.f; acc1[e] = 0.f; }

    for (int h = lane; h < H4; h += 32) {
        float4 hv0 = hrow0[h];
        float4 hv1 = hrow1[h];
#pragma unroll
        for (int e = 0; e < NEXP; e++) {
            float4 w = __ldg(&gw[(size_t)e * H4 + h]);
            acc0[e] += fmaf(hv0.x, w.x, hv0.y * w.y)
                     + fmaf(hv0.z, w.z, hv0.w * w.w);
            acc1[e] += fmaf(hv1.x, w.x, hv1.y * w.y)
                     + fmaf(hv1.z, w.z, hv1.w * w.w);
        }
    }

#pragma unroll
    for (int e = 0; e < NEXP; e++) {
#pragma unroll
        for (int off = 16; off; off >>= 1) {
            acc0[e] += __shfl_xor_sync(0xffffffffu, acc0[e], off);
            acc1[e] += __shfl_xor_sync(0xffffffffu, acc1[e], off);
        }
    }

    if (lane == 0) {
#pragma unroll
        for (int which = 0; which < 2; which++) {
            if (which == 1 && !has1) break;
            int tk = t0 + which;
            float* acc = which ? acc1 : acc0;

            float m = acc[0];
#pragma unroll
            for (int e = 1; e < NEXP; e++) m = fmaxf(m, acc[e]);
            float p[NEXP];
            float sum = 0.f;
#pragma unroll
            for (int e = 0; e < NEXP; e++) { p[e] = __expf(acc[e] - m); sum += p[e]; }
            float inv = 1.f / sum;
#pragma unroll
            for (int e = 0; e < NEXP; e++) {
                p[e] *= inv;
                g_probs[e * MAX_T + tk] = p[e];
            }
            // top-2 (lowest index wins ties, matching lax.top_k)
            float b0 = -1.f, b1 = -1.f;
            int   bi0 = 0,   bi1 = 0;
#pragma unroll
            for (int e = 0; e < NEXP; e++) {
                if (p[e] > b0)      { b1 = b0; bi1 = bi0; b0 = p[e]; bi0 = e; }
                else if (p[e] > b1) { b1 = p[e]; bi1 = e; }
            }
            float s = 1.f / (b0 + b1);
            g_s0[tk] = b0 * s;
            g_s1[tk] = b1 * s;
            g_i0[tk] = bi0;
            g_i1[tk] = bi1;
        }
    }
}

// ---------------------------------------------------------------------------
// Kernel 2: bias. grid = (V/CV chunks, token-groups). Block stages all 16
// experts' CV-float slices in smem ONCE (CV=1000, padded stride 1024 ->
// 64KB smem -> 3 blocks/SM, 24 warps/SM), then loops its 32 tokens doing
// 2x LDS.128 + FMA + streaming STG. eb L2 reads drop 524MB -> 131MB; the
// kernel becomes DRAM-write bound (262MB). Aux fused into block (0,0).
// ---------------------------------------------------------------------------
#define CV    1000
#define CVP   1024              // padded stride (floats) for LDS.128 alignment
#define CV4   (CV >> 2)         // 250 float4 per expert slice

__global__ __launch_bounds__(256, 3)
void bias_kernel(const float* __restrict__ eb,
                 float* __restrict__ out,
                 int T, int V, int tpb, int has_aux) {
    extern __shared__ float sm[];
    float4* sm4 = (float4*)sm;
    const int tid = threadIdx.x;

    // Fused aux loss (block (0,0) only; static smem, 8 warps x 2 experts)
    if (has_aux && blockIdx.x == 0 && blockIdx.y == 0) {
        __shared__ float su[NEXP];
        int w = tid >> 5, lane = tid & 31;
#pragma unroll
        for (int half = 0; half < 2; half++) {
            int e = w + half * 8;
            float s = 0.f;
            for (int t = lane; t < T; t += 32)
                s += g_probs[e * MAX_T + t];
#pragma unroll
            for (int off = 16; off; off >>= 1)
                s += __shfl_xor_sync(0xffffffffu, s, off);
            if (lane == 0) su[e] = s / (float)T;
        }
        __syncthreads();
        if (tid == 0) {
            float a = 0.f;
#pragma unroll
            for (int i = 0; i < NEXP; i++)
                a += su[i] * logf(su[i]);
            out[(size_t)T * V] = a * (float)NEXP;
        }
    }

    // Stage: 16 experts x 250 float4 into smem (padded stride 256 float4)
    const int V4 = V >> 2;
    const int c4 = blockIdx.x * CV4;            // chunk start in float4 units
    const float4* eb4 = (const float4*)eb;
    for (int i = tid; i < NEXP * CV4; i += blockDim.x) {
        int e = i / CV4;
        int v = i - e * CV4;
        sm4[e * (CVP >> 2) + v] = __ldg(&eb4[(size_t)e * V4 + c4 + v]);
    }
    __syncthreads();

    // Token loop: contiguous group of tpb tokens
    const int t0 = blockIdx.y * tpb;
    if (tid < CV4) {
        for (int i = 0; i < tpb; i++) {
            int t = t0 + i;
            if (t >= T) break;
            float s0 = g_s0[t];
            float s1 = g_s1[t];
            float4 a = sm4[g_i0[t] * (CVP >> 2) + tid];
            float4 b = sm4[g_i1[t] * (CVP >> 2) + tid];
            float4 r;
            r.x = fmaf(s0, a.x, s1 * b.x);
            r.y = fmaf(s0, a.y, s1 * b.y);
            r.z = fmaf(s0, a.z, s1 * b.z);
            r.w = fmaf(s0, a.w, s1 * b.w);
            __stcs(&((float4*)(out + (size_t)t * V))[c4 + tid], r);
        }
    }
}

extern "C" void kernel_launch(void* const* d_in, const int* in_sizes, int n_in,
                              void* d_out, int out_size) {
    const float* hs = (const float*)d_in[0];  // (T, H)
    const float* gw = (const float*)d_in[1];  // (E, H)
    const float* eb = (const float*)d_in[2];  // (E, V)
    float* out = (float*)d_out;

    int H = in_sizes[1] / NEXP;
    int T = in_sizes[0] / H;
    int V = in_sizes[2] / NEXP;
    int H4 = H >> 2;

    // 1. gating: one warp per 2 tokens, 256-thread blocks (R6 proven)
    {
        int nwarps = (T + 1) / 2;
        int threads = 256;
        int blocks = (nwarps * 32 + threads - 1) / threads;
        gate_kernel<<<blocks, threads>>>((const float4*)hs, (const float4*)gw,
                                         T, H4);
    }

    // 2. bias (+fused aux): grid = (V/CV chunks, 64 token groups)
    {
        long long tv = (long long)T * (long long)V;
        int has_aux = ((long long)out_size > tv) ? 1 : 0;
        int nchunk = V / CV;                    // 32 for V=32000
        int ngroups = 64;
        int tpb = (T + ngroups - 1) / ngroups;  // 32 tokens per block
        int smem_bytes = NEXP * CVP * (int)sizeof(float);   // 65536
        cudaFuncSetAttribute(bias_kernel,
                             cudaFuncAttributeMaxDynamicSharedMemorySize,
                             smem_bytes);
        dim3 grid(nchunk, ngroups);
        bias_kernel<<<grid, 256, smem_bytes>>>(eb, out, T, V, tpb, has_aux);
    }
}

// round 12
// speedup vs baseline: 1.1285x; 1.1285x over previous
#include <cuda_runtime.h>
#include <math.h>

#define NEXP 16
#define MAX_T 4096

// Scratch (allocation-free per harness rules)
__device__ float g_part[2 * MAX_T * NEXP]; // per-(token,half) partial logits
__device__ float g_probs[NEXP * MAX_T];    // [e][t] for coalesced aux reduce
__device__ float g_s0[MAX_T];
__device__ float g_s1[MAX_T];
__device__ int   g_i0[MAX_T];
__device__ int   g_i1[MAX_T];

// ---------------------------------------------------------------------------
// Kernel 1a: partial gating. One warp per (token, H-half): 16 dots over H/2.
// 4096 warps in 512 blocks (~27 warps/SM) -> halved latency chain + 2x more
// parallelism than the 1-phase gate. Partials stored (no atomics) ->
// deterministic.
// ---------------------------------------------------------------------------
__global__ void gate_partial(const float4* __restrict__ hs,
                             const float4* __restrict__ gw,
                             int T, int H4) {
    int task = (blockIdx.x * blockDim.x + threadIdx.x) >> 5;
    int lane = threadIdx.x & 31;
    int t    = task >> 1;
    int half = task & 1;
    if (t >= T) return;

    const int H4h = H4 >> 1;
    const int h0  = half * H4h;
    const float4* hrow = hs + (size_t)t * H4 + h0;

    float acc[NEXP];
#pragma unroll
    for (int e = 0; e < NEXP; e++) acc[e] = 0.f;

    for (int h = lane; h < H4h; h += 32) {
        float4 hv = hrow[h];
#pragma unroll
        for (int e = 0; e < NEXP; e++) {
            float4 w = __ldg(&gw[(size_t)e * H4 + h0 + h]);
            acc[e] += fmaf(hv.x, w.x, hv.y * w.y)
                    + fmaf(hv.z, w.z, hv.w * w.w);
        }
    }

#pragma unroll
    for (int e = 0; e < NEXP; e++) {
#pragma unroll
        for (int off = 16; off; off >>= 1)
            acc[e] += __shfl_xor_sync(0xffffffffu, acc[e], off);
    }

    if (lane == 0) {
        float* dst = g_part + (size_t)task * NEXP;
#pragma unroll
        for (int e = 0; e < NEXP; e++) dst[e] = acc[e];
    }
}

// ---------------------------------------------------------------------------
// Kernel 1b: finish gating. One thread per token: sum 2 partials (fixed
// order -> deterministic), softmax, top-2, renormalize.
// ---------------------------------------------------------------------------
__global__ void gate_finish(int T) {
    int t = blockIdx.x * blockDim.x + threadIdx.x;
    if (t >= T) return;

    const float* p0 = g_part + (size_t)(t * 2)     * NEXP;
    const float* p1 = g_part + (size_t)(t * 2 + 1) * NEXP;
    float l[NEXP];
#pragma unroll
    for (int e = 0; e < NEXP; e++) l[e] = p0[e] + p1[e];

    float m = l[0];
#pragma unroll
    for (int e = 1; e < NEXP; e++) m = fmaxf(m, l[e]);
    float p[NEXP];
    float sum = 0.f;
#pragma unroll
    for (int e = 0; e < NEXP; e++) { p[e] = __expf(l[e] - m); sum += p[e]; }
    float inv = 1.f / sum;
#pragma unroll
    for (int e = 0; e < NEXP; e++) {
        p[e] *= inv;
        g_probs[e * MAX_T + t] = p[e];
    }
    // top-2 (lowest index wins ties, matching lax.top_k)
    float b0 = -1.f, b1 = -1.f;
    int   bi0 = 0,   bi1 = 0;
#pragma unroll
    for (int e = 0; e < NEXP; e++) {
        if (p[e] > b0)      { b1 = b0; bi1 = bi0; b0 = p[e]; bi0 = e; }
        else if (p[e] > b1) { b1 = p[e]; bi1 = e; }
    }
    float s = 1.f / (b0 + b1);
    g_s0[t] = b0 * s;
    g_s1[t] = b1 * s;
    g_i0[t] = bi0;
    g_i1[t] = bi1;
}

// ---------------------------------------------------------------------------
// Kernel 2: bias = s0*eb[i0] + s1*eb[i1]. R6's exact proven kernel (54us,
// at the DRAM-write ceiling). 2 independent float4s/thread, __stcs streaming
// stores, eb L2-resident via __ldg. Aux fused into block (0,0).
// ---------------------------------------------------------------------------
__global__ void bias_kernel(const float* __restrict__ eb,
                            float* __restrict__ out,
                            int T, int V, int has_aux) {
    if (has_aux && blockIdx.x == 0 && blockIdx.y == 0) {
        __shared__ float su[NEXP];
        int w = threadIdx.x >> 5, lane = threadIdx.x & 31;   // 8 warps
#pragma unroll
        for (int half = 0; half < 2; half++) {
            int e = w + half * 8;
            float s = 0.f;
            for (int t = lane; t < T; t += 32)
                s += g_probs[e * MAX_T + t];
#pragma unroll
            for (int off = 16; off; off >>= 1)
                s += __shfl_xor_sync(0xffffffffu, s, off);
            if (lane == 0) su[e] = s / (float)T;
        }
        __syncthreads();
        if (threadIdx.x == 0) {
            float a = 0.f;
#pragma unroll
            for (int i = 0; i < NEXP; i++)
                a += su[i] * logf(su[i]);
            out[(size_t)T * V] = a * (float)NEXP;
        }
    }

    const int t = blockIdx.y;
    const int V4 = V >> 2;
    const float s0 = g_s0[t];
    const float s1 = g_s1[t];
    const float4* e0 = (const float4*)(eb + (size_t)g_i0[t] * V);
    const float4* e1 = (const float4*)(eb + (size_t)g_i1[t] * V);
    float4* o = (float4*)(out + (size_t)t * V);

    int base = (blockIdx.x * blockDim.x) * 2 + threadIdx.x;
    int vA = base;
    int vB = base + blockDim.x;

    if (vA < V4) {
        float4 a0 = __ldg(&e0[vA]);
        float4 b0 = __ldg(&e1[vA]);
        bool hasB = (vB < V4);
        float4 a1, b1;
        if (hasB) { a1 = __ldg(&e0[vB]); b1 = __ldg(&e1[vB]); }

        float4 r0;
        r0.x = fmaf(s0, a0.x, s1 * b0.x);
        r0.y = fmaf(s0, a0.y, s1 * b0.y);
        r0.z = fmaf(s0, a0.z, s1 * b0.z);
        r0.w = fmaf(s0, a0.w, s1 * b0.w);
        __stcs(&o[vA], r0);

        if (hasB) {
            float4 r1;
            r1.x = fmaf(s0, a1.x, s1 * b1.x);
            r1.y = fmaf(s0, a1.y, s1 * b1.y);
            r1.z = fmaf(s0, a1.z, s1 * b1.z);
            r1.w = fmaf(s0, a1.w, s1 * b1.w);
            __stcs(&o[vB], r1);
        }
    }
}

extern "C" void kernel_launch(void* const* d_in, const int* in_sizes, int n_in,
                              void* d_out, int out_size) {
    const float* hs = (const float*)d_in[0];  // (T, H)
    const float* gw = (const float*)d_in[1];  // (E, H)
    const float* eb = (const float*)d_in[2];  // (E, V)
    float* out = (float*)d_out;

    int H = in_sizes[1] / NEXP;
    int T = in_sizes[0] / H;
    int V = in_sizes[2] / NEXP;
    int H4 = H >> 2;

    // 1a. partial gating: one warp per (token, half) -> 2T warps
    {
        int nwarps = T * 2;
        int threads = 256;
        int blocks = (nwarps * 32 + threads - 1) / threads;   // 512
        gate_partial<<<blocks, threads>>>((const float4*)hs, (const float4*)gw,
                                          T, H4);
    }

    // 1b. finish gating: one thread per token
    gate_finish<<<(T + 255) / 256, 256>>>(T);

    // 2. bias (+fused aux): grid.x covers V4 with 2 float4/thread
    {
        long long tv = (long long)T * (long long)V;
        int has_aux = ((long long)out_size > tv) ? 1 : 0;
        int V4 = V >> 2;
        int threads = 256;
        int bx = (V4 + threads * 2 - 1) / (threads * 2);
        dim3 grid(bx, T);
        bias_kernel<<<grid, threads>>>(eb, out, T, V, has_aux);
    }
}